// round 7
// baseline (speedup 1.0000x reference)
#include <cuda_runtime.h>
#include <cstdint>

// Fused hinge-loss + mean, single kernel.
//   hinge = relu(lo - x)^2 + relu(x - hi)^2; hi = 1 - 0.25*y, lo = hi - 0.25;
//   valid iff 0 <= y < 4.  out = mean(Loss + hinge*valid)
//
// y is int32 on device (JAX downgrades int64 without x64 mode).
//
// Each thread processes TWO float4 groups per iteration (i, i+256) so six
// 16B loads batch per iteration (high MLP). Plain LDG (no streaming hint —
// __ldcs measured -5us regression in R4).
//
// Last block (atomicInc ticket, self-resetting) sums partials in FIXED index
// order (deterministic) + scalar tail, writes out[0].

#define RED_BLOCKS 1024
#define RED_THREADS 256

__device__ float g_partials[RED_BLOCKS];
__device__ unsigned int g_ticket;   // zero-init; atomicInc wraps -> self-reset

__device__ __forceinline__ float hinge_term(float xv, int yv) {
    bool valid = ((unsigned)yv < 4u);           // 0 <= y < 4
    int yc = valid ? yv : 0;
    float hi = fmaf((float)yc, -0.25f, 1.0f);   // SEG[y]   = 1 - 0.25*y
    float lo = hi - 0.25f;                      // SEG[y+1]
    float amin = fmaxf(lo - xv, 0.0f);
    float amax = fmaxf(xv - hi, 0.0f);
    float h = fmaf(amin, amin, amax * amax);
    return valid ? h : 0.0f;
}

__device__ __forceinline__ float group_term(float4 xv, float4 lv, int4 yv) {
    float s;
    s  = lv.x + hinge_term(xv.x, yv.x);
    s += lv.y + hinge_term(xv.y, yv.y);
    s += lv.z + hinge_term(xv.z, yv.z);
    s += lv.w + hinge_term(xv.w, yv.w);
    return s;
}

__device__ __forceinline__ float block_reduce(float acc, float* warp_sums) {
    #pragma unroll
    for (int off = 16; off > 0; off >>= 1)
        acc += __shfl_xor_sync(0xFFFFFFFFu, acc, off);
    int lane = threadIdx.x & 31;
    int wid  = threadIdx.x >> 5;
    if (lane == 0) warp_sums[wid] = acc;
    __syncthreads();
    float v = 0.0f;
    if (wid == 0) {
        v = (lane < RED_THREADS / 32) ? warp_sums[lane] : 0.0f;
        #pragma unroll
        for (int off = 16; off > 0; off >>= 1)
            v += __shfl_xor_sync(0xFFFFFFFFu, v, off);
    }
    return v;   // valid in thread 0
}

__global__ void __launch_bounds__(RED_THREADS)
hinge_fused_kernel(const float* __restrict__ x,
                   const int* __restrict__ y,
                   const float* __restrict__ L,
                   unsigned int n,       // total elements (fits 32-bit)
                   float* __restrict__ out)
{
    const float4* __restrict__ x4 = (const float4*)x;
    const float4* __restrict__ L4 = (const float4*)L;
    const int4*   __restrict__ y4 = (const int4*)y;

    const unsigned int nvec   = n >> 2;
    const unsigned int stride = 2u * RED_BLOCKS * RED_THREADS;

    float acc0 = 0.0f, acc1 = 0.0f;
    unsigned int base = blockIdx.x * (2u * RED_THREADS) + threadIdx.x;

    #pragma unroll 2
    for (; base < nvec; base += stride) {
        unsigned int i0 = base;
        unsigned int i1 = base + RED_THREADS;
        bool has1 = (i1 < nvec);
        unsigned int i1c = has1 ? i1 : i0;

        // all six loads issued before any compute -> deep MLP
        float4 xa = x4[i0];
        float4 xb = x4[i1c];
        int4   ya = y4[i0];
        int4   yb = y4[i1c];
        float4 la = L4[i0];
        float4 lb = L4[i1c];

        acc0 += group_term(xa, la, ya);
        if (has1) acc1 += group_term(xb, lb, yb);
    }
    float acc = acc0 + acc1;

    __shared__ float warp_sums[RED_THREADS / 32];
    float bsum = block_reduce(acc, warp_sums);

    // ---- publish partial, elect last block ----
    __shared__ bool is_last;
    if (threadIdx.x == 0) {
        g_partials[blockIdx.x] = bsum;
        __threadfence();   // partial visible before ticket
        unsigned int t = atomicInc(&g_ticket, RED_BLOCKS - 1);  // wraps to 0
        is_last = (t == RED_BLOCKS - 1);
    }
    __syncthreads();
    if (!is_last) return;

    // ---- last block: deterministic fixed-order final sum ----
    __threadfence();   // acquire: all partials visible
    float facc = 0.0f;
    for (unsigned int j = threadIdx.x; j < RED_BLOCKS; j += RED_THREADS)
        facc += g_partials[j];
    __syncthreads();   // reuse warp_sums safely
    float total = block_reduce(facc, warp_sums);

    if (threadIdx.x == 0) {
        // scalar tail (n % 4 != 0)
        for (unsigned int j = nvec << 2; j < n; j++)
            total += L[j] + hinge_term(x[j], y[j]);
        out[0] = total / (float)n;
    }
}

extern "C" void kernel_launch(void* const* d_in, const int* in_sizes, int n_in,
                              void* d_out, int out_size)
{
    const float* x = (const float*)d_in[0];
    const int*   y = (const int*)d_in[1];
    const float* L = (const float*)d_in[2];
    float* out = (float*)d_out;

    unsigned int n = (unsigned int)in_sizes[0];

    hinge_fused_kernel<<<RED_BLOCKS, RED_THREADS>>>(x, y, L, n, out);
}

// round 8
// speedup vs baseline: 1.0055x; 1.0055x over previous
#include <cuda_runtime.h>
#include <cstdint>

// Fused hinge-loss + mean, single kernel.
//   hinge = relu(lo - x)^2 + relu(x - hi)^2; hi = 1 - 0.25*y, lo = hi - 0.25;
//   valid iff 0 <= y < 4.  out = mean(Loss + hinge*valid)
//
// y is int32 on device (JAX downgrades int64 without x64 mode).
//
// Each thread processes TWO float4 groups per iteration (i, i+256) so six
// 16B loads batch per iteration (high MLP). Plain LDG (no streaming hint —
// __ldcs measured -5us regression in R4).
//
// Last block (atomicInc ticket, self-resetting) sums partials in FIXED index
// order (deterministic) + scalar tail, writes out[0].

#define RED_BLOCKS 1024
#define RED_THREADS 256

__device__ float g_partials[RED_BLOCKS];
__device__ unsigned int g_ticket;   // zero-init; atomicInc wraps -> self-reset

__device__ __forceinline__ float hinge_term(float xv, int yv) {
    bool valid = ((unsigned)yv < 4u);           // 0 <= y < 4
    int yc = valid ? yv : 0;
    float hi = fmaf((float)yc, -0.25f, 1.0f);   // SEG[y]   = 1 - 0.25*y
    float lo = hi - 0.25f;                      // SEG[y+1]
    float amin = fmaxf(lo - xv, 0.0f);
    float amax = fmaxf(xv - hi, 0.0f);
    float h = fmaf(amin, amin, amax * amax);
    return valid ? h : 0.0f;
}

__device__ __forceinline__ float group_term(float4 xv, float4 lv, int4 yv) {
    float s;
    s  = lv.x + hinge_term(xv.x, yv.x);
    s += lv.y + hinge_term(xv.y, yv.y);
    s += lv.z + hinge_term(xv.z, yv.z);
    s += lv.w + hinge_term(xv.w, yv.w);
    return s;
}

__device__ __forceinline__ float block_reduce(float acc, float* warp_sums) {
    #pragma unroll
    for (int off = 16; off > 0; off >>= 1)
        acc += __shfl_xor_sync(0xFFFFFFFFu, acc, off);
    int lane = threadIdx.x & 31;
    int wid  = threadIdx.x >> 5;
    if (lane == 0) warp_sums[wid] = acc;
    __syncthreads();
    float v = 0.0f;
    if (wid == 0) {
        v = (lane < RED_THREADS / 32) ? warp_sums[lane] : 0.0f;
        #pragma unroll
        for (int off = 16; off > 0; off >>= 1)
            v += __shfl_xor_sync(0xFFFFFFFFu, v, off);
    }
    return v;   // valid in thread 0
}

__global__ void __launch_bounds__(RED_THREADS)
hinge_fused_kernel(const float* __restrict__ x,
                   const int* __restrict__ y,
                   const float* __restrict__ L,
                   unsigned int n,       // total elements (fits 32-bit)
                   float* __restrict__ out)
{
    const float4* __restrict__ x4 = (const float4*)x;
    const float4* __restrict__ L4 = (const float4*)L;
    const int4*   __restrict__ y4 = (const int4*)y;

    const unsigned int nvec   = n >> 2;
    const unsigned int stride = 2u * RED_BLOCKS * RED_THREADS;

    float acc0 = 0.0f, acc1 = 0.0f;
    unsigned int base = blockIdx.x * (2u * RED_THREADS) + threadIdx.x;

    #pragma unroll 2
    for (; base < nvec; base += stride) {
        unsigned int i0 = base;
        unsigned int i1 = base + RED_THREADS;
        bool has1 = (i1 < nvec);
        unsigned int i1c = has1 ? i1 : i0;

        // all six loads issued before any compute -> deep MLP
        float4 xa = x4[i0];
        float4 xb = x4[i1c];
        int4   ya = y4[i0];
        int4   yb = y4[i1c];
        float4 la = L4[i0];
        float4 lb = L4[i1c];

        acc0 += group_term(xa, la, ya);
        if (has1) acc1 += group_term(xb, lb, yb);
    }
    float acc = acc0 + acc1;

    __shared__ float warp_sums[RED_THREADS / 32];
    float bsum = block_reduce(acc, warp_sums);

    // ---- publish partial, elect last block ----
    __shared__ bool is_last;
    if (threadIdx.x == 0) {
        g_partials[blockIdx.x] = bsum;
        __threadfence();   // partial visible before ticket
        unsigned int t = atomicInc(&g_ticket, RED_BLOCKS - 1);  // wraps to 0
        is_last = (t == RED_BLOCKS - 1);
    }
    __syncthreads();
    if (!is_last) return;

    // ---- last block: deterministic fixed-order final sum ----
    __threadfence();   // acquire: all partials visible
    float facc = 0.0f;
    for (unsigned int j = threadIdx.x; j < RED_BLOCKS; j += RED_THREADS)
        facc += g_partials[j];
    __syncthreads();   // reuse warp_sums safely
    float total = block_reduce(facc, warp_sums);

    if (threadIdx.x == 0) {
        // scalar tail (n % 4 != 0)
        for (unsigned int j = nvec << 2; j < n; j++)
            total += L[j] + hinge_term(x[j], y[j]);
        out[0] = total / (float)n;
    }
}

extern "C" void kernel_launch(void* const* d_in, const int* in_sizes, int n_in,
                              void* d_out, int out_size)
{
    const float* x = (const float*)d_in[0];
    const int*   y = (const int*)d_in[1];
    const float* L = (const float*)d_in[2];
    float* out = (float*)d_out;

    unsigned int n = (unsigned int)in_sizes[0];

    hinge_fused_kernel<<<RED_BLOCKS, RED_THREADS>>>(x, y, L, n, out);
}